// round 1
// baseline (speedup 1.0000x reference)
#include <cuda_runtime.h>
#include <math.h>

#define BATCHN 2
#define SEQLENN 4096
#define DIMN 1024
#define DSTATE 64
#define DCONVN 4
#define DINNER 2048
#define NHEADSN 32
#define CONVD 2176          // D_INNER + 2*D_STATE
#define DPROJ 4256          // 2*D_INNER + 2*D_STATE + NHEADS
#define NROWS (BATCHN*SEQLENN)   // 8192
#define NSPLIT 4            // state-dim split for the scan
#define TCH 32              // timesteps staged per scan chunk
#define EPSV 1e-5f

// ------------------------- scratch (no allocs allowed) -------------------------
__device__ float g_zxbcdt[(size_t)NROWS * DPROJ];            // in_proj output
__device__ float g_xBCc[(size_t)NROWS * CONVD];              // conv+silu output
__device__ float g_dt[(size_t)NROWS * NHEADSN];              // softplus dt
__device__ float g_ypart[(size_t)NSPLIT * NROWS * DINNER];   // partial scan outputs
__device__ float g_yn[(size_t)NROWS * DINNER];               // gated+normed y
__device__ float g_H[(size_t)NROWS * DIMN];                  // out_proj output
__device__ float g_HKV[(size_t)NROWS * DINNER];              // to_h output

// ------------------------- GEMM: C[M,N] = A[M,K] @ B[N,K]^T -------------------------
// 128x128 tile, 256 threads, 8x8 per-thread, K-step 16.
__global__ __launch_bounds__(256) void gemm_nt(
    const float* __restrict__ A, const float* __restrict__ B,
    float* __restrict__ C, int M, int N, int K)
{
    __shared__ __align__(16) float As[16][128];
    __shared__ __align__(16) float Bs[16][128];
    const int tid = threadIdx.x;
    const int bm = blockIdx.y * 128;
    const int bn = blockIdx.x * 128;
    const int tx = tid & 15;    // 0..15 -> 8 cols each
    const int ty = tid >> 4;    // 0..15 -> 8 rows each

    float acc[8][8];
#pragma unroll
    for (int i = 0; i < 8; i++)
#pragma unroll
        for (int j = 0; j < 8; j++) acc[i][j] = 0.f;

    for (int k0 = 0; k0 < K; k0 += 16) {
#pragma unroll
        for (int ld = 0; ld < 2; ld++) {
            int idx = tid + ld * 256;           // 0..511 float4 slots
            int r = idx >> 2;                   // 0..127
            int kk = (idx & 3) << 2;            // 0,4,8,12
            float4 v = make_float4(0.f, 0.f, 0.f, 0.f);
            int gr = bm + r;
            if (gr < M) v = *(const float4*)(A + (size_t)gr * K + k0 + kk);
            As[kk + 0][r] = v.x; As[kk + 1][r] = v.y;
            As[kk + 2][r] = v.z; As[kk + 3][r] = v.w;
        }
#pragma unroll
        for (int ld = 0; ld < 2; ld++) {
            int idx = tid + ld * 256;
            int r = idx >> 2;
            int kk = (idx & 3) << 2;
            float4 v = make_float4(0.f, 0.f, 0.f, 0.f);
            int gr = bn + r;
            if (gr < N) v = *(const float4*)(B + (size_t)gr * K + k0 + kk);
            Bs[kk + 0][r] = v.x; Bs[kk + 1][r] = v.y;
            Bs[kk + 2][r] = v.z; Bs[kk + 3][r] = v.w;
        }
        __syncthreads();
#pragma unroll
        for (int kk = 0; kk < 16; kk++) {
            float a[8], b[8];
            float4 a0 = *(const float4*)&As[kk][ty * 8];
            float4 a1 = *(const float4*)&As[kk][ty * 8 + 4];
            float4 b0 = *(const float4*)&Bs[kk][tx * 8];
            float4 b1 = *(const float4*)&Bs[kk][tx * 8 + 4];
            a[0]=a0.x; a[1]=a0.y; a[2]=a0.z; a[3]=a0.w;
            a[4]=a1.x; a[5]=a1.y; a[6]=a1.z; a[7]=a1.w;
            b[0]=b0.x; b[1]=b0.y; b[2]=b0.z; b[3]=b0.w;
            b[4]=b1.x; b[5]=b1.y; b[6]=b1.z; b[7]=b1.w;
#pragma unroll
            for (int i = 0; i < 8; i++)
#pragma unroll
                for (int j = 0; j < 8; j++)
                    acc[i][j] = fmaf(a[i], b[j], acc[i][j]);
        }
        __syncthreads();
    }
#pragma unroll
    for (int i = 0; i < 8; i++) {
        int gr = bm + ty * 8 + i;
        if (gr >= M) continue;
#pragma unroll
        for (int j = 0; j < 8; j++) {
            int gc = bn + tx * 8 + j;
            if (gc < N) C[(size_t)gr * N + gc] = acc[i][j];
        }
    }
}

// ------------------------- dt = softplus(dt_raw + dt_bias) -------------------------
__global__ void dt_kernel(const float* __restrict__ dt_bias)
{
    int idx = blockIdx.x * blockDim.x + threadIdx.x;
    if (idx >= NROWS * NHEADSN) return;
    int h = idx & (NHEADSN - 1);
    int row = idx >> 5;
    float v = g_zxbcdt[(size_t)row * DPROJ + (DINNER + CONVD) + h] + dt_bias[h];
    float sp = (v > 20.f) ? v : log1pf(expf(v));
    g_dt[idx] = sp;
}

// ------------------------- depthwise causal conv (w=4) + bias + SiLU -------------------------
__global__ void conv_silu_kernel(const float* __restrict__ cw, const float* __restrict__ cb)
{
    size_t idx = (size_t)blockIdx.x * blockDim.x + threadIdx.x;
    if (idx >= (size_t)NROWS * CONVD) return;
    int c = (int)(idx % CONVD);
    size_t bl = idx / CONVD;
    int l = (int)(bl % SEQLENN);
    int b = (int)(bl / SEQLENN);
    float acc = cb[c];
#pragma unroll
    for (int k = 0; k < DCONVN; k++) {
        int lt = l - (DCONVN - 1) + k;
        if (lt >= 0)
            acc = fmaf(cw[c * DCONVN + k],
                       g_zxbcdt[(size_t)(b * SEQLENN + lt) * DPROJ + DINNER + c], acc);
    }
    float sg = 1.f / (1.f + expf(-acc));
    g_xBCc[idx] = acc * sg;
}

// ------------------------- selective scan -------------------------
// grid = B * NHEADS * NSPLIT blocks; each block: one (b,h) pair and a 16-wide
// slice of the state dim. 256 threads: p = tid>>2 (0..63), sub = tid&3 owns 4 n's.
__global__ __launch_bounds__(256) void scan_kernel(const float* __restrict__ A_log)
{
    const int bid = blockIdx.x;
    const int ns = bid & (NSPLIT - 1);
    const int h = (bid >> 2) & (NHEADSN - 1);
    const int b = bid >> 7;
    const int tid = threadIdx.x;
    const int p = tid >> 2;
    const int sub = tid & 3;
    const float Ah = -expf(A_log[h]);
    const int nbase = ns * (DSTATE / NSPLIT);   // 16-wide slice

    __shared__ __align__(16) float s_x[TCH][64];
    __shared__ __align__(16) float s_B[TCH][16];
    __shared__ __align__(16) float s_C[TCH][16];
    __shared__ float s_dt[TCH];
    __shared__ float s_dA[TCH];
    __shared__ float s_y[TCH][64];

    float hreg[4] = {0.f, 0.f, 0.f, 0.f};

    for (int t0 = 0; t0 < SEQLENN; t0 += TCH) {
        for (int i = tid; i < TCH * 64; i += 256) {
            int t = i >> 6, pp = i & 63;
            s_x[t][pp] = g_xBCc[(size_t)(b * SEQLENN + t0 + t) * CONVD + h * 64 + pp];
        }
        for (int i = tid; i < TCH * 16; i += 256) {
            int t = i >> 4, nn = i & 15;
            size_t ro = (size_t)(b * SEQLENN + t0 + t) * CONVD;
            s_B[t][nn] = g_xBCc[ro + DINNER + nbase + nn];
            s_C[t][nn] = g_xBCc[ro + DINNER + DSTATE + nbase + nn];
        }
        if (tid < TCH) {
            float dtv = g_dt[(size_t)(b * SEQLENN + t0 + tid) * NHEADSN + h];
            s_dt[tid] = dtv;
            s_dA[tid] = expf(dtv * Ah);
        }
        __syncthreads();
#pragma unroll 4
        for (int t = 0; t < TCH; t++) {
            float dA = s_dA[t];
            float dtx = s_dt[t] * s_x[t][p];
            float4 Bv = *(const float4*)&s_B[t][sub * 4];
            float4 Cv = *(const float4*)&s_C[t][sub * 4];
            float part;
            hreg[0] = fmaf(hreg[0], dA, dtx * Bv.x); part  = hreg[0] * Cv.x;
            hreg[1] = fmaf(hreg[1], dA, dtx * Bv.y); part = fmaf(hreg[1], Cv.y, part);
            hreg[2] = fmaf(hreg[2], dA, dtx * Bv.z); part = fmaf(hreg[2], Cv.z, part);
            hreg[3] = fmaf(hreg[3], dA, dtx * Bv.w); part = fmaf(hreg[3], Cv.w, part);
            part += __shfl_down_sync(0xffffffffu, part, 2, 4);
            part += __shfl_down_sync(0xffffffffu, part, 1, 4);
            if (sub == 0) s_y[t][p] = part;
        }
        __syncthreads();
        for (int i = tid; i < TCH * 64; i += 256) {
            int t = i >> 6, pp = i & 63;
            g_ypart[((size_t)ns * NROWS + (size_t)(b * SEQLENN + t0 + t)) * DINNER + h * 64 + pp]
                = s_y[t][pp];
        }
        __syncthreads();
    }
}

// ------------------------- combine partials + D*x, gate with silu(z), RMSNorm -------------------------
__global__ __launch_bounds__(256) void gate_norm_kernel(
    const float* __restrict__ Dp, const float* __restrict__ norm_w)
{
    const int row = blockIdx.x;       // 0..NROWS-1
    const int tid = threadIdx.x;      // 256
    const size_t YP = (size_t)NROWS * DINNER;
    float vals[8];
    float ss = 0.f;
#pragma unroll
    for (int j = 0; j < 8; j++) {
        int c = tid + j * 256;
        size_t yi = (size_t)row * DINNER + c;
        float y = g_ypart[yi] + g_ypart[YP + yi] + g_ypart[2 * YP + yi] + g_ypart[3 * YP + yi];
        int hh = c >> 6;
        float xv = g_xBCc[(size_t)row * CONVD + c];
        y = fmaf(Dp[hh], xv, y);
        float zv = g_zxbcdt[(size_t)row * DPROJ + c];
        float g = zv / (1.f + expf(-zv));
        float v = y * g;
        vals[j] = v;
        ss = fmaf(v, v, ss);
    }
    __shared__ float red[32];
    for (int o = 16; o; o >>= 1) ss += __shfl_down_sync(0xffffffffu, ss, o);
    if ((tid & 31) == 0) red[tid >> 5] = ss;
    __syncthreads();
    if (tid < 32) {
        float s2 = (tid < 8) ? red[tid] : 0.f;
        for (int o = 4; o; o >>= 1) s2 += __shfl_down_sync(0xffffffffu, s2, o);
        if (tid == 0) red[0] = s2;
    }
    __syncthreads();
    float scale = rsqrtf(red[0] / (float)DINNER + EPSV);
#pragma unroll
    for (int j = 0; j < 8; j++) {
        int c = tid + j * 256;
        g_yn[(size_t)row * DINNER + c] = vals[j] * scale * norm_w[c];
    }
}

// ------------------------- split HKV -> HK | HV -------------------------
__global__ void split_kernel(float* __restrict__ out)
{
    size_t idx = (size_t)blockIdx.x * blockDim.x + threadIdx.x;
    if (idx >= (size_t)NROWS * DINNER) return;
    size_t row = idx / DINNER;
    int c = (int)(idx % DINNER);
    float v = g_HKV[idx];
    if (c < DIMN)
        out[row * DIMN + c] = v;
    else
        out[(size_t)NROWS * DIMN + row * DIMN + (c - DIMN)] = v;
}

// ------------------------- launch -------------------------
extern "C" void kernel_launch(void* const* d_in, const int* in_sizes, int n_in,
                              void* d_out, int out_size)
{
    const float* X          = (const float*)d_in[0];
    const float* in_proj_w  = (const float*)d_in[1];
    const float* conv_w     = (const float*)d_in[2];
    const float* conv_b     = (const float*)d_in[3];
    const float* dt_bias    = (const float*)d_in[4];
    const float* A_log      = (const float*)d_in[5];
    const float* Dp         = (const float*)d_in[6];
    const float* norm_w     = (const float*)d_in[7];
    const float* out_proj_w = (const float*)d_in[8];
    const float* to_h_w     = (const float*)d_in[9];
    float* out = (float*)d_out;

    float *zx, *yn, *H, *HKV;
    cudaGetSymbolAddress((void**)&zx,  g_zxbcdt);
    cudaGetSymbolAddress((void**)&yn,  g_yn);
    cudaGetSymbolAddress((void**)&H,   g_H);
    cudaGetSymbolAddress((void**)&HKV, g_HKV);

    // 1) zxbcdt = X @ in_proj_w^T
    gemm_nt<<<dim3((DPROJ + 127) / 128, NROWS / 128), 256>>>(X, in_proj_w, zx, NROWS, DPROJ, DIMN);
    // 2) dt = softplus(dt_raw + bias)
    dt_kernel<<<(NROWS * NHEADSN + 255) / 256, 256>>>(dt_bias);
    // 3) depthwise conv + silu
    conv_silu_kernel<<<(int)(((size_t)NROWS * CONVD + 255) / 256), 256>>>(conv_w, conv_b);
    // 4) selective scan (state-split into 4 partials)
    scan_kernel<<<BATCHN * NHEADSN * NSPLIT, 256>>>(A_log);
    // 5) combine + gate + rmsnorm
    gate_norm_kernel<<<NROWS, 256>>>(Dp, norm_w);
    // 6) H = yn @ out_proj_w^T
    gemm_nt<<<dim3(DIMN / 128, NROWS / 128), 256>>>(yn, out_proj_w, H, NROWS, DIMN, DINNER);
    // 7) HKV = H @ to_h_w^T
    gemm_nt<<<dim3(DINNER / 128, NROWS / 128), 256>>>(H, to_h_w, HKV, NROWS, DINNER, DIMN);
    // 8) split into HK | HV
    split_kernel<<<(int)(((size_t)NROWS * DINNER + 255) / 256), 256>>>(out);
}

// round 2
// speedup vs baseline: 1.2765x; 1.2765x over previous
#include <cuda_runtime.h>
#include <math.h>
#include <stdint.h>

#define BATCHN 2
#define SEQLENN 4096
#define DIMN 1024
#define DSTATE 64
#define DCONVN 4
#define DINNER 2048
#define NHEADSN 32
#define CONVD 2176          // D_INNER + 2*D_STATE
#define DPROJ 4256          // 2*D_INNER + 2*D_STATE + NHEADS
#define NROWS (BATCHN*SEQLENN)   // 8192
#define NSPLIT 8            // state-dim split for the scan
#define TCH 32              // timesteps staged per scan chunk
#define EPSV 1e-5f

// ------------------------- scratch (no allocs allowed) -------------------------
__device__ float g_zxbcdt[(size_t)NROWS * DPROJ];            // in_proj output
__device__ float g_xBCc[(size_t)NROWS * CONVD];              // conv+silu output
__device__ float g_dt[(size_t)NROWS * NHEADSN];              // softplus dt
__device__ float g_ypart[(size_t)NSPLIT * NROWS * DINNER];   // partial scan outputs
__device__ float g_yn[(size_t)NROWS * DINNER];               // gated+normed y
__device__ float g_H[(size_t)NROWS * DIMN];                  // out_proj output
__device__ float g_HKV[(size_t)NROWS * DINNER];              // to_h output

// ------------------------- TF32 helpers -------------------------
__device__ __forceinline__ uint32_t f2tf32(float x) {
    uint32_t r;
    asm("cvt.rna.tf32.f32 %0, %1;" : "=r"(r) : "f"(x));
    return r;
}

#define MMA_TF32(c, a, b) \
    asm volatile("mma.sync.aligned.m16n8k8.row.col.f32.tf32.tf32.f32 " \
        "{%0,%1,%2,%3}, {%4,%5,%6,%7}, {%8,%9}, {%0,%1,%2,%3};" \
        : "+f"((c)[0]), "+f"((c)[1]), "+f"((c)[2]), "+f"((c)[3]) \
        : "r"((a)[0]), "r"((a)[1]), "r"((a)[2]), "r"((a)[3]), \
          "r"((b)[0]), "r"((b)[1]))

// ------------------------- tensor-core GEMM: C[M,N] = A[M,K] @ B[N,K]^T -------------------------
// 128x128 tile, 256 threads (8 warps, 2x4), warp tile 64x32.
// 3xTF32 error-corrected: a*b ~= ah*bh + ah*bl + al*bh.
__global__ __launch_bounds__(256) void gemm_nt_tc(
    const float* __restrict__ A, const float* __restrict__ B,
    float* __restrict__ C, int M, int N, int K)
{
    __shared__ uint32_t Ah[16][132];
    __shared__ uint32_t Al[16][132];
    __shared__ uint32_t Bh[16][132];
    __shared__ uint32_t Bl[16][132];

    const int tid  = threadIdx.x;
    const int bm   = blockIdx.y * 128;
    const int bn   = blockIdx.x * 128;
    const int lane = tid & 31;
    const int warp = tid >> 5;
    const int wm   = (warp >> 2) * 64;   // 0 or 64
    const int wn   = (warp & 3) * 32;    // 0,32,64,96
    const int grp  = lane >> 2;          // 0..7
    const int qid  = lane & 3;           // 0..3

    float acc[4][4][4];
#pragma unroll
    for (int i = 0; i < 4; i++)
#pragma unroll
        for (int j = 0; j < 4; j++)
#pragma unroll
            for (int e = 0; e < 4; e++) acc[i][j][e] = 0.f;

    for (int k0 = 0; k0 < K; k0 += 16) {
        // stage A tile (128 x 16) with hi/lo tf32 split
#pragma unroll
        for (int ld = 0; ld < 2; ld++) {
            int idx = tid + ld * 256;
            int r = idx >> 2;
            int kk = (idx & 3) << 2;
            int gr = bm + r;
            float4 v = make_float4(0.f, 0.f, 0.f, 0.f);
            if (gr < M) v = *(const float4*)(A + (size_t)gr * K + k0 + kk);
            float xs[4] = {v.x, v.y, v.z, v.w};
#pragma unroll
            for (int e = 0; e < 4; e++) {
                uint32_t hb = f2tf32(xs[e]);
                float hf = __uint_as_float(hb);
                uint32_t lb = f2tf32(xs[e] - hf);
                Ah[kk + e][r] = hb;
                Al[kk + e][r] = lb;
            }
        }
        // stage B tile (128 x 16)
#pragma unroll
        for (int ld = 0; ld < 2; ld++) {
            int idx = tid + ld * 256;
            int r = idx >> 2;
            int kk = (idx & 3) << 2;
            int gr = bn + r;
            float4 v = make_float4(0.f, 0.f, 0.f, 0.f);
            if (gr < N) v = *(const float4*)(B + (size_t)gr * K + k0 + kk);
            float xs[4] = {v.x, v.y, v.z, v.w};
#pragma unroll
            for (int e = 0; e < 4; e++) {
                uint32_t hb = f2tf32(xs[e]);
                float hf = __uint_as_float(hb);
                uint32_t lb = f2tf32(xs[e] - hf);
                Bh[kk + e][r] = hb;
                Bl[kk + e][r] = lb;
            }
        }
        __syncthreads();

#pragma unroll
        for (int ks = 0; ks < 16; ks += 8) {
            uint32_t ah[4][4], al[4][4];
#pragma unroll
            for (int mf = 0; mf < 4; mf++) {
                int r0 = wm + mf * 16 + grp;
                ah[mf][0] = Ah[ks + qid][r0];
                ah[mf][1] = Ah[ks + qid][r0 + 8];
                ah[mf][2] = Ah[ks + qid + 4][r0];
                ah[mf][3] = Ah[ks + qid + 4][r0 + 8];
                al[mf][0] = Al[ks + qid][r0];
                al[mf][1] = Al[ks + qid][r0 + 8];
                al[mf][2] = Al[ks + qid + 4][r0];
                al[mf][3] = Al[ks + qid + 4][r0 + 8];
            }
            uint32_t bh[4][2], bl[4][2];
#pragma unroll
            for (int nf = 0; nf < 4; nf++) {
                int c0 = wn + nf * 8 + grp;
                bh[nf][0] = Bh[ks + qid][c0];
                bh[nf][1] = Bh[ks + qid + 4][c0];
                bl[nf][0] = Bl[ks + qid][c0];
                bl[nf][1] = Bl[ks + qid + 4][c0];
            }
#pragma unroll
            for (int mf = 0; mf < 4; mf++)
#pragma unroll
                for (int nf = 0; nf < 4; nf++) {
                    MMA_TF32(acc[mf][nf], ah[mf], bh[nf]);
                    MMA_TF32(acc[mf][nf], ah[mf], bl[nf]);
                    MMA_TF32(acc[mf][nf], al[mf], bh[nf]);
                }
        }
        __syncthreads();
    }

    // writeback
#pragma unroll
    for (int mf = 0; mf < 4; mf++) {
        int gr0 = bm + wm + mf * 16 + grp;
        int gr1 = gr0 + 8;
#pragma unroll
        for (int nf = 0; nf < 4; nf++) {
            int gc = bn + wn + nf * 8 + 2 * qid;
            if (gc < N) {
                if (gr0 < M) {
                    C[(size_t)gr0 * N + gc]     = acc[mf][nf][0];
                    C[(size_t)gr0 * N + gc + 1] = acc[mf][nf][1];
                }
                if (gr1 < M) {
                    C[(size_t)gr1 * N + gc]     = acc[mf][nf][2];
                    C[(size_t)gr1 * N + gc + 1] = acc[mf][nf][3];
                }
            }
        }
    }
}

// ------------------------- dt = softplus(dt_raw + dt_bias) -------------------------
__global__ void dt_kernel(const float* __restrict__ dt_bias)
{
    int idx = blockIdx.x * blockDim.x + threadIdx.x;
    if (idx >= NROWS * NHEADSN) return;
    int h = idx & (NHEADSN - 1);
    int row = idx >> 5;
    float v = g_zxbcdt[(size_t)row * DPROJ + (DINNER + CONVD) + h] + dt_bias[h];
    float sp = (v > 20.f) ? v : log1pf(expf(v));
    g_dt[idx] = sp;
}

// ------------------------- depthwise causal conv (w=4) + bias + SiLU -------------------------
__global__ void conv_silu_kernel(const float* __restrict__ cw, const float* __restrict__ cb)
{
    size_t idx = (size_t)blockIdx.x * blockDim.x + threadIdx.x;
    if (idx >= (size_t)NROWS * CONVD) return;
    int c = (int)(idx % CONVD);
    size_t bl = idx / CONVD;
    int l = (int)(bl % SEQLENN);
    int b = (int)(bl / SEQLENN);
    float acc = cb[c];
#pragma unroll
    for (int k = 0; k < DCONVN; k++) {
        int lt = l - (DCONVN - 1) + k;
        if (lt >= 0)
            acc = fmaf(cw[c * DCONVN + k],
                       g_zxbcdt[(size_t)(b * SEQLENN + lt) * DPROJ + DINNER + c], acc);
    }
    float sg = 1.f / (1.f + expf(-acc));
    g_xBCc[idx] = acc * sg;
}

// ------------------------- selective scan -------------------------
// grid = B * NHEADS * NSPLIT blocks; each block: one (b,h) pair and an 8-wide
// slice of the state dim. 256 threads: p = tid>>2 (0..63), sub = tid&3 owns 2 n's.
__global__ __launch_bounds__(256) void scan_kernel(const float* __restrict__ A_log)
{
    const int bid = blockIdx.x;
    const int ns = bid & (NSPLIT - 1);
    const int h = (bid >> 3) & (NHEADSN - 1);
    const int b = bid >> 8;
    const int tid = threadIdx.x;
    const int p = tid >> 2;
    const int sub = tid & 3;
    const float Ah = -expf(A_log[h]);
    const int nbase = ns * (DSTATE / NSPLIT);   // 8-wide slice

    __shared__ __align__(16) float s_x[TCH][64];
    __shared__ __align__(16) float s_B[TCH][8];
    __shared__ __align__(16) float s_C[TCH][8];
    __shared__ float s_dt[TCH];
    __shared__ float s_dA[TCH];
    __shared__ float s_y[TCH][64];

    float hreg[2] = {0.f, 0.f};

    for (int t0 = 0; t0 < SEQLENN; t0 += TCH) {
        for (int i = tid; i < TCH * 64; i += 256) {
            int t = i >> 6, pp = i & 63;
            s_x[t][pp] = g_xBCc[(size_t)(b * SEQLENN + t0 + t) * CONVD + h * 64 + pp];
        }
        for (int i = tid; i < TCH * 8; i += 256) {
            int t = i >> 3, nn = i & 7;
            size_t ro = (size_t)(b * SEQLENN + t0 + t) * CONVD;
            s_B[t][nn] = g_xBCc[ro + DINNER + nbase + nn];
            s_C[t][nn] = g_xBCc[ro + DINNER + DSTATE + nbase + nn];
        }
        if (tid < TCH) {
            float dtv = g_dt[(size_t)(b * SEQLENN + t0 + tid) * NHEADSN + h];
            s_dt[tid] = dtv;
            s_dA[tid] = expf(dtv * Ah);
        }
        __syncthreads();
#pragma unroll 4
        for (int t = 0; t < TCH; t++) {
            float dA = s_dA[t];
            float dtx = s_dt[t] * s_x[t][p];
            float2 Bv = *(const float2*)&s_B[t][sub * 2];
            float2 Cv = *(const float2*)&s_C[t][sub * 2];
            float part;
            hreg[0] = fmaf(hreg[0], dA, dtx * Bv.x); part = hreg[0] * Cv.x;
            hreg[1] = fmaf(hreg[1], dA, dtx * Bv.y); part = fmaf(hreg[1], Cv.y, part);
            part += __shfl_down_sync(0xffffffffu, part, 2, 4);
            part += __shfl_down_sync(0xffffffffu, part, 1, 4);
            if (sub == 0) s_y[t][p] = part;
        }
        __syncthreads();
        for (int i = tid; i < TCH * 64; i += 256) {
            int t = i >> 6, pp = i & 63;
            g_ypart[((size_t)ns * NROWS + (size_t)(b * SEQLENN + t0 + t)) * DINNER + h * 64 + pp]
                = s_y[t][pp];
        }
        __syncthreads();
    }
}

// ------------------------- combine partials + D*x, gate with silu(z), RMSNorm -------------------------
__global__ __launch_bounds__(256) void gate_norm_kernel(
    const float* __restrict__ Dp, const float* __restrict__ norm_w)
{
    const int row = blockIdx.x;       // 0..NROWS-1
    const int tid = threadIdx.x;      // 256
    const size_t YP = (size_t)NROWS * DINNER;
    float vals[8];
    float ss = 0.f;
#pragma unroll
    for (int j = 0; j < 8; j++) {
        int c = tid + j * 256;
        size_t yi = (size_t)row * DINNER + c;
        float y = 0.f;
#pragma unroll
        for (int s = 0; s < NSPLIT; s++) y += g_ypart[(size_t)s * YP + yi];
        int hh = c >> 6;
        float xv = g_xBCc[(size_t)row * CONVD + c];
        y = fmaf(Dp[hh], xv, y);
        float zv = g_zxbcdt[(size_t)row * DPROJ + c];
        float g = zv / (1.f + expf(-zv));
        float v = y * g;
        vals[j] = v;
        ss = fmaf(v, v, ss);
    }
    __shared__ float red[32];
    for (int o = 16; o; o >>= 1) ss += __shfl_down_sync(0xffffffffu, ss, o);
    if ((tid & 31) == 0) red[tid >> 5] = ss;
    __syncthreads();
    if (tid < 32) {
        float s2 = (tid < 8) ? red[tid] : 0.f;
        for (int o = 4; o; o >>= 1) s2 += __shfl_down_sync(0xffffffffu, s2, o);
        if (tid == 0) red[0] = s2;
    }
    __syncthreads();
    float scale = rsqrtf(red[0] / (float)DINNER + EPSV);
#pragma unroll
    for (int j = 0; j < 8; j++) {
        int c = tid + j * 256;
        g_yn[(size_t)row * DINNER + c] = vals[j] * scale * norm_w[c];
    }
}

// ------------------------- split HKV -> HK | HV -------------------------
__global__ void split_kernel(float* __restrict__ out)
{
    size_t idx = (size_t)blockIdx.x * blockDim.x + threadIdx.x;
    if (idx >= (size_t)NROWS * DINNER) return;
    size_t row = idx / DINNER;
    int c = (int)(idx % DINNER);
    float v = g_HKV[idx];
    if (c < DIMN)
        out[row * DIMN + c] = v;
    else
        out[(size_t)NROWS * DIMN + row * DIMN + (c - DIMN)] = v;
}

// ------------------------- launch -------------------------
extern "C" void kernel_launch(void* const* d_in, const int* in_sizes, int n_in,
                              void* d_out, int out_size)
{
    const float* X          = (const float*)d_in[0];
    const float* in_proj_w  = (const float*)d_in[1];
    const float* conv_w     = (const float*)d_in[2];
    const float* conv_b     = (const float*)d_in[3];
    const float* dt_bias    = (const float*)d_in[4];
    const float* A_log      = (const float*)d_in[5];
    const float* Dp         = (const float*)d_in[6];
    const float* norm_w     = (const float*)d_in[7];
    const float* out_proj_w = (const float*)d_in[8];
    const float* to_h_w     = (const float*)d_in[9];
    float* out = (float*)d_out;

    float *zx, *yn, *H, *HKV;
    cudaGetSymbolAddress((void**)&zx,  g_zxbcdt);
    cudaGetSymbolAddress((void**)&yn,  g_yn);
    cudaGetSymbolAddress((void**)&H,   g_H);
    cudaGetSymbolAddress((void**)&HKV, g_HKV);

    // 1) zxbcdt = X @ in_proj_w^T
    gemm_nt_tc<<<dim3((DPROJ + 127) / 128, NROWS / 128), 256>>>(X, in_proj_w, zx, NROWS, DPROJ, DIMN);
    // 2) dt = softplus(dt_raw + bias)
    dt_kernel<<<(NROWS * NHEADSN + 255) / 256, 256>>>(dt_bias);
    // 3) depthwise conv + silu
    conv_silu_kernel<<<(int)(((size_t)NROWS * CONVD + 255) / 256), 256>>>(conv_w, conv_b);
    // 4) selective scan (state-split into 8 partials)
    scan_kernel<<<BATCHN * NHEADSN * NSPLIT, 256>>>(A_log);
    // 5) combine + gate + rmsnorm
    gate_norm_kernel<<<NROWS, 256>>>(Dp, norm_w);
    // 6) H = yn @ out_proj_w^T
    gemm_nt_tc<<<dim3(DIMN / 128, NROWS / 128), 256>>>(yn, out_proj_w, H, NROWS, DIMN, DINNER);
    // 7) HKV = H @ to_h_w^T
    gemm_nt_tc<<<dim3(DINNER / 128, NROWS / 128), 256>>>(H, to_h_w, HKV, NROWS, DINNER, DIMN);
    // 8) split into HK | HV
    split_kernel<<<(int)(((size_t)NROWS * DINNER + 255) / 256), 256>>>(out);
}

// round 3
// speedup vs baseline: 1.7461x; 1.3678x over previous
#include <cuda_runtime.h>
#include <cuda_bf16.h>
#include <math.h>
#include <stdint.h>

#define BATCHN 2
#define SEQLENN 4096
#define DIMN 1024
#define DSTATE 64
#define DCONVN 4
#define DINNER 2048
#define NHEADSN 32
#define CONVD 2176          // D_INNER + 2*D_STATE
#define DPROJ 4256          // 2*D_INNER + 2*D_STATE + NHEADS
#define NROWS (BATCHN*SEQLENN)   // 8192
#define NSPLIT 8            // state-dim split for the scan
#define TCH 32              // timesteps staged per scan chunk
#define EPSV 1e-5f

// ------------------------- scratch (no allocs allowed) -------------------------
__device__ float g_zxbcdt[(size_t)NROWS * DPROJ];            // in_proj output
__device__ float g_xBCc[(size_t)NROWS * CONVD];              // conv+silu output
__device__ float g_dt[(size_t)NROWS * NHEADSN];              // softplus dt
__device__ float g_ypart[(size_t)NSPLIT * NROWS * DINNER];   // partial scan outputs
__device__ float g_yn[(size_t)NROWS * DINNER];               // gated+normed y
__device__ float g_H[(size_t)NROWS * DIMN];                  // out_proj output
__device__ float g_HKV[(size_t)NROWS * DINNER];              // to_h output

// ------------------------- bf16 helpers -------------------------
__device__ __forceinline__ uint32_t pack_hi(float a, float b, float& ra, float& rb) {
    __nv_bfloat162 h = __floats2bfloat162_rn(a, b);   // x=a (low), y=b (high)
    ra = a - __bfloat162float(h.x);
    rb = b - __bfloat162float(h.y);
    return *(uint32_t*)&h;
}
__device__ __forceinline__ uint32_t pack_lo(float a, float b) {
    __nv_bfloat162 h = __floats2bfloat162_rn(a, b);
    return *(uint32_t*)&h;
}

#define MMA_BF16(c, a, b) \
    asm volatile("mma.sync.aligned.m16n8k16.row.col.f32.bf16.bf16.f32 " \
        "{%0,%1,%2,%3}, {%4,%5,%6,%7}, {%8,%9}, {%0,%1,%2,%3};" \
        : "+f"((c)[0]), "+f"((c)[1]), "+f"((c)[2]), "+f"((c)[3]) \
        : "r"((a)[0]), "r"((a)[1]), "r"((a)[2]), "r"((a)[3]), \
          "r"((b)[0]), "r"((b)[1]))

// ------------------------- tensor-core GEMM: C[M,N] = A[M,K] @ B[N,K]^T -------------------------
// 128x128 tile, 256 threads (8 warps, 2x4), warp tile 64x32, K-step 16.
// 3x bf16 error-corrected: a*b ~= ah*bh + ah*bl + al*bh. Register prefetch pipeline.
__global__ __launch_bounds__(256) void gemm_nt_tc(
    const float* __restrict__ A, const float* __restrict__ B,
    float* __restrict__ C, int M, int N, int K)
{
    // [k-pair 0..7][row 0..127 + pad to 136] packed bf16x2 (even k = low half)
    __shared__ uint32_t Ah[8][136];
    __shared__ uint32_t Al[8][136];
    __shared__ uint32_t Bh[8][136];
    __shared__ uint32_t Bl[8][136];

    const int tid  = threadIdx.x;
    const int bm   = blockIdx.y * 128;
    const int bn   = blockIdx.x * 128;
    const int lane = tid & 31;
    const int warp = tid >> 5;
    const int wm   = (warp >> 2) * 64;   // 0 or 64
    const int wn   = (warp & 3) * 32;    // 0,32,64,96
    const int grp  = lane >> 2;          // 0..7
    const int qid  = lane & 3;           // 0..3

    // staging coords: each thread handles 2 rows (A) + 2 rows (B), 4 k each
    const int sr0 = tid >> 2;            // 0..63
    const int sr1 = sr0 + 64;            // 64..127
    const int skk = (tid & 3) << 2;      // 0,4,8,12
    const int spp = skk >> 1;            // k-pair base: 0,2,4,6

    float acc[4][4][4];
#pragma unroll
    for (int i = 0; i < 4; i++)
#pragma unroll
        for (int j = 0; j < 4; j++)
#pragma unroll
            for (int e = 0; e < 4; e++) acc[i][j][e] = 0.f;

    float4 av[2], bv[2];
    {
        const float4 z4 = make_float4(0.f, 0.f, 0.f, 0.f);
        av[0] = (bm + sr0 < M) ? *(const float4*)(A + (size_t)(bm + sr0) * K + skk) : z4;
        av[1] = (bm + sr1 < M) ? *(const float4*)(A + (size_t)(bm + sr1) * K + skk) : z4;
        bv[0] = (bn + sr0 < N) ? *(const float4*)(B + (size_t)(bn + sr0) * K + skk) : z4;
        bv[1] = (bn + sr1 < N) ? *(const float4*)(B + (size_t)(bn + sr1) * K + skk) : z4;
    }

    for (int k0 = 0; k0 < K; k0 += 16) {
        // stage current registers -> smem (hi/lo bf16x2)
#pragma unroll
        for (int half = 0; half < 2; half++) {
            int r = half ? sr1 : sr0;
            float4 v = av[half];
            float rx, ry, rz, rw;
            Ah[spp    ][r] = pack_hi(v.x, v.y, rx, ry);
            Ah[spp + 1][r] = pack_hi(v.z, v.w, rz, rw);
            Al[spp    ][r] = pack_lo(rx, ry);
            Al[spp + 1][r] = pack_lo(rz, rw);
            v = bv[half];
            Bh[spp    ][r] = pack_hi(v.x, v.y, rx, ry);
            Bh[spp + 1][r] = pack_hi(v.z, v.w, rz, rw);
            Bl[spp    ][r] = pack_lo(rx, ry);
            Bl[spp + 1][r] = pack_lo(rz, rw);
        }
        __syncthreads();

        // prefetch next tile into registers (overlaps with MMA below)
        if (k0 + 16 < K) {
            const float4 z4 = make_float4(0.f, 0.f, 0.f, 0.f);
            int kn = k0 + 16 + skk;
            av[0] = (bm + sr0 < M) ? *(const float4*)(A + (size_t)(bm + sr0) * K + kn) : z4;
            av[1] = (bm + sr1 < M) ? *(const float4*)(A + (size_t)(bm + sr1) * K + kn) : z4;
            bv[0] = (bn + sr0 < N) ? *(const float4*)(B + (size_t)(bn + sr0) * K + kn) : z4;
            bv[1] = (bn + sr1 < N) ? *(const float4*)(B + (size_t)(bn + sr1) * K + kn) : z4;
        }

        // fragments: m16n8k16. a0:(r,kp qid) a1:(r+8,kp qid) a2:(r,kp qid+4) a3:(r+8,kp qid+4)
        uint32_t ah[4][4], al[4][4];
#pragma unroll
        for (int mf = 0; mf < 4; mf++) {
            int r0 = wm + mf * 16 + grp;
            ah[mf][0] = Ah[qid    ][r0];
            ah[mf][1] = Ah[qid    ][r0 + 8];
            ah[mf][2] = Ah[qid + 4][r0];
            ah[mf][3] = Ah[qid + 4][r0 + 8];
            al[mf][0] = Al[qid    ][r0];
            al[mf][1] = Al[qid    ][r0 + 8];
            al[mf][2] = Al[qid + 4][r0];
            al[mf][3] = Al[qid + 4][r0 + 8];
        }
        uint32_t bh[4][2], bl[4][2];
#pragma unroll
        for (int nf = 0; nf < 4; nf++) {
            int c0 = wn + nf * 8 + grp;
            bh[nf][0] = Bh[qid    ][c0];
            bh[nf][1] = Bh[qid + 4][c0];
            bl[nf][0] = Bl[qid    ][c0];
            bl[nf][1] = Bl[qid + 4][c0];
        }
#pragma unroll
        for (int mf = 0; mf < 4; mf++)
#pragma unroll
            for (int nf = 0; nf < 4; nf++) {
                MMA_BF16(acc[mf][nf], ah[mf], bh[nf]);
                MMA_BF16(acc[mf][nf], ah[mf], bl[nf]);
                MMA_BF16(acc[mf][nf], al[mf], bh[nf]);
            }
        __syncthreads();
    }

    // writeback
#pragma unroll
    for (int mf = 0; mf < 4; mf++) {
        int gr0 = bm + wm + mf * 16 + grp;
        int gr1 = gr0 + 8;
#pragma unroll
        for (int nf = 0; nf < 4; nf++) {
            int gc = bn + wn + nf * 8 + 2 * qid;
            if (gc < N) {
                if (gr0 < M) {
                    C[(size_t)gr0 * N + gc]     = acc[mf][nf][0];
                    C[(size_t)gr0 * N + gc + 1] = acc[mf][nf][1];
                }
                if (gr1 < M) {
                    C[(size_t)gr1 * N + gc]     = acc[mf][nf][2];
                    C[(size_t)gr1 * N + gc + 1] = acc[mf][nf][3];
                }
            }
        }
    }
}

// ------------------------- dt = softplus(dt_raw + dt_bias) -------------------------
__global__ void dt_kernel(const float* __restrict__ dt_bias)
{
    int idx = blockIdx.x * blockDim.x + threadIdx.x;
    if (idx >= NROWS * NHEADSN) return;
    int h = idx & (NHEADSN - 1);
    int row = idx >> 5;
    float v = g_zxbcdt[(size_t)row * DPROJ + (DINNER + CONVD) + h] + dt_bias[h];
    float sp = (v > 20.f) ? v : log1pf(expf(v));
    g_dt[idx] = sp;
}

// ------------------------- depthwise causal conv (w=4) + bias + SiLU -------------------------
__global__ void conv_silu_kernel(const float* __restrict__ cw, const float* __restrict__ cb)
{
    size_t idx = (size_t)blockIdx.x * blockDim.x + threadIdx.x;
    if (idx >= (size_t)NROWS * CONVD) return;
    int c = (int)(idx % CONVD);
    size_t bl = idx / CONVD;
    int l = (int)(bl % SEQLENN);
    int b = (int)(bl / SEQLENN);
    float acc = cb[c];
#pragma unroll
    for (int k = 0; k < DCONVN; k++) {
        int lt = l - (DCONVN - 1) + k;
        if (lt >= 0)
            acc = fmaf(cw[c * DCONVN + k],
                       g_zxbcdt[(size_t)(b * SEQLENN + lt) * DPROJ + DINNER + c], acc);
    }
    float sg = 1.f / (1.f + expf(-acc));
    g_xBCc[idx] = acc * sg;
}

// ------------------------- selective scan -------------------------
__global__ __launch_bounds__(256) void scan_kernel(const float* __restrict__ A_log)
{
    const int bid = blockIdx.x;
    const int ns = bid & (NSPLIT - 1);
    const int h = (bid >> 3) & (NHEADSN - 1);
    const int b = bid >> 8;
    const int tid = threadIdx.x;
    const int p = tid >> 2;
    const int sub = tid & 3;
    const float Ah = -expf(A_log[h]);
    const int nbase = ns * (DSTATE / NSPLIT);   // 8-wide slice

    __shared__ __align__(16) float s_x[TCH][64];
    __shared__ __align__(16) float s_B[TCH][8];
    __shared__ __align__(16) float s_C[TCH][8];
    __shared__ __align__(16) float2 s_dtA[TCH];
    __shared__ float s_y[TCH][64];

    float hreg[2] = {0.f, 0.f};

    for (int t0 = 0; t0 < SEQLENN; t0 += TCH) {
        for (int i = tid; i < TCH * 64; i += 256) {
            int t = i >> 6, pp = i & 63;
            s_x[t][pp] = g_xBCc[(size_t)(b * SEQLENN + t0 + t) * CONVD + h * 64 + pp];
        }
        for (int i = tid; i < TCH * 8; i += 256) {
            int t = i >> 3, nn = i & 7;
            size_t ro = (size_t)(b * SEQLENN + t0 + t) * CONVD;
            s_B[t][nn] = g_xBCc[ro + DINNER + nbase + nn];
            s_C[t][nn] = g_xBCc[ro + DINNER + DSTATE + nbase + nn];
        }
        if (tid < TCH) {
            float dtv = g_dt[(size_t)(b * SEQLENN + t0 + tid) * NHEADSN + h];
            s_dtA[tid] = make_float2(dtv, expf(dtv * Ah));
        }
        __syncthreads();
#pragma unroll 4
        for (int t = 0; t < TCH; t++) {
            float2 dd = s_dtA[t];
            float dtx = dd.x * s_x[t][p];
            float2 Bv = *(const float2*)&s_B[t][sub * 2];
            float2 Cv = *(const float2*)&s_C[t][sub * 2];
            float part;
            hreg[0] = fmaf(hreg[0], dd.y, dtx * Bv.x); part = hreg[0] * Cv.x;
            hreg[1] = fmaf(hreg[1], dd.y, dtx * Bv.y); part = fmaf(hreg[1], Cv.y, part);
            part += __shfl_down_sync(0xffffffffu, part, 2, 4);
            part += __shfl_down_sync(0xffffffffu, part, 1, 4);
            if (sub == 0) s_y[t][p] = part;
        }
        __syncthreads();
        for (int i = tid; i < TCH * 64; i += 256) {
            int t = i >> 6, pp = i & 63;
            g_ypart[((size_t)ns * NROWS + (size_t)(b * SEQLENN + t0 + t)) * DINNER + h * 64 + pp]
                = s_y[t][pp];
        }
        __syncthreads();
    }
}

// ------------------------- combine partials + D*x, gate with silu(z), RMSNorm -------------------------
__global__ __launch_bounds__(256) void gate_norm_kernel(
    const float* __restrict__ Dp, const float* __restrict__ norm_w)
{
    const int row = blockIdx.x;       // 0..NROWS-1
    const int tid = threadIdx.x;      // 256
    const size_t YP = (size_t)NROWS * DINNER;
    float vals[8];
    float ss = 0.f;
#pragma unroll
    for (int j = 0; j < 8; j++) {
        int c = tid + j * 256;
        size_t yi = (size_t)row * DINNER + c;
        float y = 0.f;
#pragma unroll
        for (int s = 0; s < NSPLIT; s++) y += g_ypart[(size_t)s * YP + yi];
        int hh = c >> 6;
        float xv = g_xBCc[(size_t)row * CONVD + c];
        y = fmaf(Dp[hh], xv, y);
        float zv = g_zxbcdt[(size_t)row * DPROJ + c];
        float g = zv / (1.f + expf(-zv));
        float v = y * g;
        vals[j] = v;
        ss = fmaf(v, v, ss);
    }
    __shared__ float red[32];
    for (int o = 16; o; o >>= 1) ss += __shfl_down_sync(0xffffffffu, ss, o);
    if ((tid & 31) == 0) red[tid >> 5] = ss;
    __syncthreads();
    if (tid < 32) {
        float s2 = (tid < 8) ? red[tid] : 0.f;
        for (int o = 4; o; o >>= 1) s2 += __shfl_down_sync(0xffffffffu, s2, o);
        if (tid == 0) red[0] = s2;
    }
    __syncthreads();
    float scale = rsqrtf(red[0] / (float)DINNER + EPSV);
#pragma unroll
    for (int j = 0; j < 8; j++) {
        int c = tid + j * 256;
        g_yn[(size_t)row * DINNER + c] = vals[j] * scale * norm_w[c];
    }
}

// ------------------------- split HKV -> HK | HV -------------------------
__global__ void split_kernel(float* __restrict__ out)
{
    size_t idx = (size_t)blockIdx.x * blockDim.x + threadIdx.x;
    if (idx >= (size_t)NROWS * DINNER) return;
    size_t row = idx / DINNER;
    int c = (int)(idx % DINNER);
    float v = g_HKV[idx];
    if (c < DIMN)
        out[row * DIMN + c] = v;
    else
        out[(size_t)NROWS * DIMN + row * DIMN + (c - DIMN)] = v;
}

// ------------------------- launch -------------------------
extern "C" void kernel_launch(void* const* d_in, const int* in_sizes, int n_in,
                              void* d_out, int out_size)
{
    const float* X          = (const float*)d_in[0];
    const float* in_proj_w  = (const float*)d_in[1];
    const float* conv_w     = (const float*)d_in[2];
    const float* conv_b     = (const float*)d_in[3];
    const float* dt_bias    = (const float*)d_in[4];
    const float* A_log      = (const float*)d_in[5];
    const float* Dp         = (const float*)d_in[6];
    const float* norm_w     = (const float*)d_in[7];
    const float* out_proj_w = (const float*)d_in[8];
    const float* to_h_w     = (const float*)d_in[9];
    float* out = (float*)d_out;

    float *zx, *yn, *H, *HKV;
    cudaGetSymbolAddress((void**)&zx,  g_zxbcdt);
    cudaGetSymbolAddress((void**)&yn,  g_yn);
    cudaGetSymbolAddress((void**)&H,   g_H);
    cudaGetSymbolAddress((void**)&HKV, g_HKV);

    // 1) zxbcdt = X @ in_proj_w^T
    gemm_nt_tc<<<dim3((DPROJ + 127) / 128, NROWS / 128), 256>>>(X, in_proj_w, zx, NROWS, DPROJ, DIMN);
    // 2) dt = softplus(dt_raw + bias)
    dt_kernel<<<(NROWS * NHEADSN + 255) / 256, 256>>>(dt_bias);
    // 3) depthwise conv + silu
    conv_silu_kernel<<<(int)(((size_t)NROWS * CONVD + 255) / 256), 256>>>(conv_w, conv_b);
    // 4) selective scan (state-split into 8 partials)
    scan_kernel<<<BATCHN * NHEADSN * NSPLIT, 256>>>(A_log);
    // 5) combine + gate + rmsnorm
    gate_norm_kernel<<<NROWS, 256>>>(Dp, norm_w);
    // 6) H = yn @ out_proj_w^T
    gemm_nt_tc<<<dim3(DIMN / 128, NROWS / 128), 256>>>(yn, out_proj_w, H, NROWS, DIMN, DINNER);
    // 7) HKV = H @ to_h_w^T
    gemm_nt_tc<<<dim3(DINNER / 128, NROWS / 128), 256>>>(H, to_h_w, HKV, NROWS, DINNER, DIMN);
    // 8) split into HK | HV
    split_kernel<<<(int)(((size_t)NROWS * DINNER + 255) / 256), 256>>>(out);
}